// round 16
// baseline (speedup 1.0000x reference)
#include <cuda_runtime.h>
#include <cuda_fp16.h>
#include <cstdint>

#define BB 4
#define NN 16384
#define CC 256
#define HH 8
#define DD 64
#define HD 512
#define OUTC 256
#define NCH 32           // split-K chunks over the grid axis for G
#define KCH 512          // tokens per chunk

// static device scratch
__device__ float g_Gp[BB*NCH*CC*CC];     // per-chunk partials of G = U^T U
__device__ float g_sup[BB*NCH*CC];       // per-chunk column sums of U
__device__ float g_G[BB*CC*CC];          // reduced Gram matrices
__device__ float g_su[BB*CC];            // reduced column sums
__device__ float g_P[2*BB*HH*DD*CC];     // P[leg][bh] = W_h @ G   (64 x 256)
__device__ float g_ssp[2*BB*HH*4*DD];    // per-otile partials of diag(P W^T)
__device__ float g_smp[2*BB*HH*4*DD];    // per-otile partials of W @ su
__device__ float g_T[BB*CC*HD];          // Wq_h^T @ kvhat, [b][c][h*64+e]
__device__ unsigned g_Fh2[BB*OUTC*(CC/2)]; // F^T as half2 c-pairs: [b][o][cpair]

__device__ __forceinline__ unsigned packh2(float lo, float hi) {
    __half2 h = __floats2half2_rn(lo, hi);   // .x (low bits) = lo = even index
    return *reinterpret_cast<unsigned*>(&h);
}
__device__ __forceinline__ float2 unpackh2(unsigned w) {
    __half2 h = *reinterpret_cast<__half2*>(&w);
    return __half22float2(h);
}

#define MMA16(accp, a0, a1, a2, a3, b0, b1) \
    asm volatile( \
        "mma.sync.aligned.m16n8k16.row.col.f32.f16.f16.f32 " \
        "{%0,%1,%2,%3}, {%4,%5,%6,%7}, {%8,%9}, {%0,%1,%2,%3};" \
        : "+f"((accp)[0]), "+f"((accp)[1]), "+f"((accp)[2]), "+f"((accp)[3]) \
        : "r"(a0), "r"(a1), "r"(a2), "r"(a3), "r"(b0), "r"(b1))

// ---------------------------------------------------------------------------
// k_g: split-K syrk partials via fp16 m16n8k16 mma, double-buffered smem
// (one __syncthreads per 16-token slab).
// ---------------------------------------------------------------------------
__global__ __launch_bounds__(256) void k_g(const float* __restrict__ U) {
    __shared__ unsigned Us2[2][256][9];     // [buf][ch][tokpair], pad 9
    const int tile = blockIdx.x;            // 0..2
    const int ti = tile >> 1, tj = (tile + 1) >> 1;
    const int ch = blockIdx.y, b = blockIdx.z;
    const int tid = threadIdx.x;
    const int wid = tid >> 5, lane = tid & 31;
    const int warp_m = wid & 3, warp_n = wid >> 2;
    const int gr = lane >> 2, tc = lane & 3;
    const bool diag = (ti == tj);

    const float* Up = U + (size_t)(b * NN + ch * KCH) * CC;

    float acc[2][8][4];
    #pragma unroll
    for (int mi = 0; mi < 2; mi++)
        #pragma unroll
        for (int ni = 0; ni < 8; ni++)
            #pragma unroll
            for (int q = 0; q < 4; q++) acc[mi][ni][q] = 0.f;
    float s = 0.f;

    const int tp  = tid & 7;
    const int chb = (tid >> 3) * 8;

    float4 v0a, v0b, v1a, v1b;
    {
        const float* r0 = Up + (size_t)(2 * tp) * CC + chb;
        const float* r1 = Up + (size_t)(2 * tp + 1) * CC + chb;
        v0a = *(const float4*)r0;       v0b = *(const float4*)(r0 + 4);
        v1a = *(const float4*)r1;       v1b = *(const float4*)(r1 + 4);
    }

    for (int sl = 0; sl < KCH / 16; sl++) {
        const int buf = sl & 1;
        unsigned w[8];
        w[0] = packh2(v0a.x, v1a.x); w[1] = packh2(v0a.y, v1a.y);
        w[2] = packh2(v0a.z, v1a.z); w[3] = packh2(v0a.w, v1a.w);
        w[4] = packh2(v0b.x, v1b.x); w[5] = packh2(v0b.y, v1b.y);
        w[6] = packh2(v0b.z, v1b.z); w[7] = packh2(v0b.w, v1b.w);
        #pragma unroll
        for (int i = 0; i < 8; i++) Us2[buf][chb + i][tp] = w[i];
        __syncthreads();

        if (sl + 1 < KCH / 16) {
            const int t0 = (sl + 1) * 16;
            const float* r0 = Up + (size_t)(t0 + 2 * tp) * CC + chb;
            const float* r1 = Up + (size_t)(t0 + 2 * tp + 1) * CC + chb;
            v0a = *(const float4*)r0;   v0b = *(const float4*)(r0 + 4);
            v1a = *(const float4*)r1;   v1b = *(const float4*)(r1 + 4);
        }

        if (tile == 1) {
            #pragma unroll
            for (int p = 0; p < 8; p++) {
                float2 f = unpackh2(Us2[buf][tid][p]);
                s += f.x + f.y;
            }
        }

        unsigned a0[2], a1[2], a2[2], a3[2];
        #pragma unroll
        for (int mi = 0; mi < 2; mi++) {
            const int am = ti * 128 + warp_m * 16 + mi * 64;
            a0[mi] = Us2[buf][am + gr][tc];
            a1[mi] = Us2[buf][am + gr + 8][tc];
            a2[mi] = Us2[buf][am + gr][tc + 4];
            a3[mi] = Us2[buf][am + gr + 8][tc + 4];
        }
        #pragma unroll
        for (int ni = 0; ni < 8; ni++) {
            const int nb = warp_n * 8 + ni * 16;
            const int bn = tj * 128 + nb;
            unsigned b0 = Us2[buf][bn + gr][tc];
            unsigned b1 = Us2[buf][bn + gr][tc + 4];
            #pragma unroll
            for (int mi = 0; mi < 2; mi++) {
                const int mr = warp_m * 16 + mi * 64;
                if (diag && (nb + 8 <= mr)) continue;
                MMA16(acc[mi][ni], a0[mi], a1[mi], a2[mi], a3[mi], b0, b1);
            }
        }
    }

    float* op = g_Gp + (size_t)(b * NCH + ch) * CC * CC;
    #pragma unroll
    for (int mi = 0; mi < 2; mi++) {
        const int mr = warp_m * 16 + mi * 64;
        #pragma unroll
        for (int ni = 0; ni < 8; ni++) {
            const int nb = warp_n * 8 + ni * 16;
            if (diag && (nb + 8 <= mr)) continue;
            const int row = ti * 128 + mr + gr;
            const int col = tj * 128 + nb + tc * 2;
            float2 c0v = make_float2(acc[mi][ni][0], acc[mi][ni][1]);
            float2 c1v = make_float2(acc[mi][ni][2], acc[mi][ni][3]);
            *(float2*)(op + (size_t)row * CC + col) = c0v;
            *(float2*)(op + (size_t)(row + 8) * CC + col) = c1v;
        }
    }
    if (tile == 1) g_sup[(size_t)(b * NCH + ch) * CC + tid] = s;
}

// ---------------------------------------------------------------------------
// kA: reduce split-K partials -> g_G, g_su (symmetry reconstruct).
// ---------------------------------------------------------------------------
__global__ __launch_bounds__(256) void kA() {
    const int r = blockIdx.x, b = blockIdx.y, c = threadIdx.x;
    int rr = r, cc = c;
    const bool swap = ((r >= 128) && (c < 128)) ||
                      (((r >= 128) == (c >= 128)) && (c < r));
    if (swap) { rr = c; cc = r; }
    float s = 0.f;
    for (int ch = 0; ch < NCH; ch++)
        s += g_Gp[((size_t)(b * NCH + ch) * CC + rr) * CC + cc];
    g_G[((size_t)b * CC + r) * CC + c] = s;
    if (r == 0) {
        float t = 0.f;
        for (int ch = 0; ch < NCH; ch++)
            t += g_sup[(size_t)(b * NCH + ch) * CC + c];
        g_su[(size_t)b * CC + c] = t;
    }
}

// ---------------------------------------------------------------------------
// kB1: P[leg][b,h] = W_h @ G, double-buffered (1 sync per K-step).
// Epilogue emits per-otile stat partials.
// ---------------------------------------------------------------------------
__global__ __launch_bounds__(256) void kB1(const float* __restrict__ Wk,
                                           const float* __restrict__ Wv) {
    __shared__ float As[2][16][68];
    __shared__ float Bs[2][16][68];
    const int bh = blockIdx.x, leg = blockIdx.y, ot = blockIdx.z;
    const int b = bh >> 3, h = bh & 7;
    const float* W  = (leg ? Wv : Wk) + (size_t)h * DD * CC;
    const float* Gb = g_G + (size_t)b * CC * CC;
    const int o0 = ot * 64;
    const int tid = threadIdx.x;
    const int tx = tid & 15, ty = tid >> 4;

    const int ad = tid >> 2, akq = (tid & 3) * 4;
    const int bk = tid >> 4, bc4 = (tid & 15) * 4;

    float acc[4][4];
    #pragma unroll
    for (int i = 0; i < 4; i++)
        #pragma unroll
        for (int j = 0; j < 4; j++) acc[i][j] = 0.f;

    float4 wA = *(const float4*)(W + (size_t)ad * CC + akq);
    float4 wB = *(const float4*)(Gb + (size_t)bk * CC + o0 + bc4);

    for (int it = 0; it < CC / 16; it++) {
        const int buf = it & 1;
        As[buf][akq + 0][ad] = wA.x; As[buf][akq + 1][ad] = wA.y;
        As[buf][akq + 2][ad] = wA.z; As[buf][akq + 3][ad] = wA.w;
        *(float4*)&Bs[buf][bk][bc4] = wB;
        __syncthreads();
        if (it + 1 < CC / 16) {
            const int kt = (it + 1) * 16;
            wA = *(const float4*)(W + (size_t)ad * CC + kt + akq);
            wB = *(const float4*)(Gb + (size_t)(kt + bk) * CC + o0 + bc4);
        }
        #pragma unroll
        for (int k = 0; k < 16; k++) {
            float4 a4 = *(const float4*)&As[buf][k][ty * 4];
            float4 b4 = *(const float4*)&Bs[buf][k][tx * 4];
            float aa[4] = {a4.x, a4.y, a4.z, a4.w};
            float bb[4] = {b4.x, b4.y, b4.z, b4.w};
            #pragma unroll
            for (int i = 0; i < 4; i++)
                #pragma unroll
                for (int j = 0; j < 4; j++)
                    acc[i][j] = fmaf(aa[i], bb[j], acc[i][j]);
        }
    }
    __syncthreads();    // protect smem reuse below (last iter had no sync)

    float* op = g_P + (size_t)(leg * BB * HH + bh) * DD * CC;
    const float4 su4 = *(const float4*)(g_su + (size_t)b * CC + o0 + tx * 4);
    float* red_ss = &As[0][0][0];     // reuse smem: 64 x 16
    float* red_sm = &Bs[0][0][0];
    #pragma unroll
    for (int i = 0; i < 4; i++) {
        const int d = ty * 4 + i;
        #pragma unroll
        for (int j = 0; j < 4; j++)
            op[(size_t)d * CC + o0 + tx * 4 + j] = acc[i][j];
        float4 w4 = *(const float4*)(W + (size_t)d * CC + o0 + tx * 4);
        float ssp = acc[i][0] * w4.x + acc[i][1] * w4.y
                  + acc[i][2] * w4.z + acc[i][3] * w4.w;
        float smp = w4.x * su4.x + w4.y * su4.y + w4.z * su4.z + w4.w * su4.w;
        red_ss[d * 16 + tx] = ssp;
        red_sm[d * 16 + tx] = smp;
    }
    __syncthreads();
    if (tid < 64) {
        float ss = 0.f, sm = 0.f;
        #pragma unroll
        for (int t = 0; t < 16; t++) {
            ss += red_ss[tid * 16 + t];
            sm += red_sm[tid * 16 + t];
        }
        const size_t idx = (size_t)((leg * BB * HH + bh) * 4 + ot) * DD + tid;
        g_ssp[idx] = ss;
        g_smp[idx] = sm;
    }
}

// ---------------------------------------------------------------------------
// kB2T: e-split, double-buffered. grid (4 etiles, 32 bh).
// ---------------------------------------------------------------------------
__global__ __launch_bounds__(256) void kB2T(const float* __restrict__ Wv,
                                            const float* __restrict__ Wq) {
    __shared__ float As[2][16][68];
    __shared__ float Bs[2][16][20];
    __shared__ float mk[64], rk[64], mv[16], rv[16];
    __shared__ __align__(16) float kvs[64][16];
    const int et = blockIdx.x, e0 = et * 16;
    const int bh = blockIdx.y;
    const int b = bh >> 3, h = bh & 7;
    const int tid = threadIdx.x;
    const int tx = tid & 15, ty = tid >> 4;
    const float invN = 1.f / NN;

    const float* Pk  = g_P + (size_t)bh * DD * CC;
    const float* WvH = Wv + (size_t)h * DD * CC;

    const int ad = tid >> 2, akq = (tid & 3) * 4;

    float acc[4];
    #pragma unroll
    for (int i = 0; i < 4; i++) acc[i] = 0.f;

    float4 pA = *(const float4*)(Pk + (size_t)ad * CC + akq);
    float4 pB;
    if (tid < 64)
        pB = *(const float4*)(WvH + (size_t)(e0 + (tid >> 2)) * CC + akq);

    // stats from kB1 partials (overlaps GEMM loads)
    if (tid < 64) {
        const int d = tid;
        const float* sp = g_ssp + (size_t)bh * 4 * DD + d;
        const float* mp = g_smp + (size_t)bh * 4 * DD + d;
        float ss = sp[0] + sp[64] + sp[128] + sp[192];
        float sm = mp[0] + mp[64] + mp[128] + mp[192];
        const float m = sm * invN;
        mk[d] = m; rk[d] = rsqrtf(ss * invN - m * m + 1e-5f);
    } else if (tid < 80) {
        const int e = tid - 64;
        const int row = e0 + e;
        const float* sp = g_ssp + (size_t)(BB * HH + bh) * 4 * DD + row;
        const float* mp = g_smp + (size_t)(BB * HH + bh) * 4 * DD + row;
        float ss = sp[0] + sp[64] + sp[128] + sp[192];
        float sm = mp[0] + mp[64] + mp[128] + mp[192];
        const float m = sm * invN;
        mv[e] = m; rv[e] = rsqrtf(ss * invN - m * m + 1e-5f);
    }

    for (int it = 0; it < CC / 16; it++) {
        const int buf = it & 1;
        As[buf][akq + 0][ad] = pA.x; As[buf][akq + 1][ad] = pA.y;
        As[buf][akq + 2][ad] = pA.z; As[buf][akq + 3][ad] = pA.w;
        if (tid < 64) {
            const int e = tid >> 2;
            Bs[buf][akq + 0][e] = pB.x; Bs[buf][akq + 1][e] = pB.y;
            Bs[buf][akq + 2][e] = pB.z; Bs[buf][akq + 3][e] = pB.w;
        }
        __syncthreads();
        if (it + 1 < CC / 16) {
            const int kt = (it + 1) * 16;
            pA = *(const float4*)(Pk + (size_t)ad * CC + kt + akq);
            if (tid < 64)
                pB = *(const float4*)(WvH + (size_t)(e0 + (tid >> 2)) * CC + kt + akq);
        }
        #pragma unroll
        for (int k = 0; k < 16; k++) {
            float4 a4 = *(const float4*)&As[buf][k][ty * 4];
            float bb = Bs[buf][k][tx];
            acc[0] = fmaf(a4.x, bb, acc[0]);
            acc[1] = fmaf(a4.y, bb, acc[1]);
            acc[2] = fmaf(a4.z, bb, acc[2]);
            acc[3] = fmaf(a4.w, bb, acc[3]);
        }
    }

    #pragma unroll
    for (int i = 0; i < 4; i++) {
        const int d = ty * 4 + i;
        kvs[d][tx] = rk[d] * rv[tx] * (acc[i] * invN - mk[d] * mv[tx]);
    }
    __syncthreads();

    float accT[16];
    #pragma unroll
    for (int e = 0; e < 16; e++) accT[e] = 0.f;
    const int c = tid;
    #pragma unroll 8
    for (int d = 0; d < DD; d++) {
        const float wq = Wq[(size_t)(h * DD + d) * CC + c];
        #pragma unroll
        for (int e4 = 0; e4 < 4; e4++) {
            float4 t = *(const float4*)&kvs[d][e4 * 4];
            accT[e4*4+0] = fmaf(wq, t.x, accT[e4*4+0]);
            accT[e4*4+1] = fmaf(wq, t.y, accT[e4*4+1]);
            accT[e4*4+2] = fmaf(wq, t.z, accT[e4*4+2]);
            accT[e4*4+3] = fmaf(wq, t.w, accT[e4*4+3]);
        }
    }
    float* Tp = g_T + ((size_t)b * CC + c) * HD + h * DD + e0;
    #pragma unroll
    for (int e4 = 0; e4 < 4; e4++)
        *(float4*)(Tp + e4 * 4) = make_float4(accT[e4*4+0], accT[e4*4+1],
                                              accT[e4*4+2], accT[e4*4+3]);
}

// ---------------------------------------------------------------------------
// k3c_F: F = T @ Wo^T, double-buffered; stores half2 c-pairs into g_Fh2.
// ---------------------------------------------------------------------------
__global__ __launch_bounds__(256) void k3c_F(const float* __restrict__ Wo) {
    __shared__ float As[2][16][68];
    __shared__ float Bs[2][16][68];
    const int o0 = blockIdx.x * 64;
    const int c0 = blockIdx.y * 64;
    const int b  = blockIdx.z;
    const int tid = threadIdx.x;
    const int tx = tid & 15, ty = tid >> 4;
    const int ar = tid >> 2, akq = (tid & 3) * 4;

    const float* Tb = g_T + (size_t)b * CC * HD;

    float acc[4][4];
    #pragma unroll
    for (int i = 0; i < 4; i++)
        #pragma unroll
        for (int j = 0; j < 4; j++) acc[i][j] = 0.f;

    float4 tA = *(const float4*)(Tb + (size_t)(c0 + ar) * HD + akq);
    float4 tB = *(const float4*)(Wo + (size_t)(o0 + ar) * HD + akq);

    for (int it = 0; it < HD / 16; it++) {
        const int buf = it & 1;
        As[buf][akq + 0][ar] = tA.x; As[buf][akq + 1][ar] = tA.y;
        As[buf][akq + 2][ar] = tA.z; As[buf][akq + 3][ar] = tA.w;
        Bs[buf][akq + 0][ar] = tB.x; Bs[buf][akq + 1][ar] = tB.y;
        Bs[buf][akq + 2][ar] = tB.z; Bs[buf][akq + 3][ar] = tB.w;
        __syncthreads();
        if (it + 1 < HD / 16) {
            const int j0 = (it + 1) * 16;
            tA = *(const float4*)(Tb + (size_t)(c0 + ar) * HD + j0 + akq);
            tB = *(const float4*)(Wo + (size_t)(o0 + ar) * HD + j0 + akq);
        }
        #pragma unroll
        for (int k = 0; k < 16; k++) {
            float4 a4 = *(const float4*)&As[buf][k][ty * 4];
            float4 b4 = *(const float4*)&Bs[buf][k][tx * 4];
            float aa[4] = {a4.x, a4.y, a4.z, a4.w};
            float bb[4] = {b4.x, b4.y, b4.z, b4.w};
            #pragma unroll
            for (int i = 0; i < 4; i++)
                #pragma unroll
                for (int j = 0; j < 4; j++)
                    acc[i][j] = fmaf(aa[i], bb[j], acc[i][j]);
        }
    }

    const int cw0 = (c0 + ty * 4) >> 1;   // c-pair index
    #pragma unroll
    for (int j = 0; j < 4; j++) {
        const int o = o0 + tx * 4 + j;
        unsigned* Fr = g_Fh2 + ((size_t)(b * OUTC + o) << 7);
        Fr[cw0]     = packh2(acc[0][j], acc[1][j]);
        Fr[cw0 + 1] = packh2(acc[2][j], acc[3][j]);
    }
}

// ---------------------------------------------------------------------------
// k4_mma: out = U @ F + bo via fp16 m16n8k16, single n-pass (CTA 128x256),
// double-buffered dynamic smem (1 sync per 32-K chunk).
// ---------------------------------------------------------------------------
#define K4_AW (128 * 20)                 // words per A buffer
#define K4_BW (256 * 20)                 // words per B buffer
#define K4_SMEM ((2 * K4_AW + 2 * K4_BW) * 4)

__global__ __launch_bounds__(512) void k4_mma(const float* __restrict__ U,
                                              const float* __restrict__ bo,
                                              float* __restrict__ out) {
    extern __shared__ unsigned sm4[];
    unsigned* Abuf[2] = { sm4, sm4 + K4_AW };
    unsigned* Bbuf[2] = { sm4 + 2 * K4_AW, sm4 + 2 * K4_AW + K4_BW };

    const int tid = threadIdx.x;
    const int wid = tid >> 5, lane = tid & 31;
    const int warp_m = wid & 3;
    const int warp_n = wid >> 2;        // 0..3
    const int gr = lane >> 2;
    const int tc = lane & 3;

    const int mt0 = blockIdx.x * 128;
    const int b   = mt0 >> 14;

    float acc[2][8][4];
    #pragma unroll
    for (int mi = 0; mi < 2; mi++)
        #pragma unroll
        for (int ni = 0; ni < 8; ni++)
            #pragma unroll
            for (int q = 0; q < 4; q++) acc[mi][ni][q] = 0.f;

    const int arow = tid >> 2;           // 0..127
    const int akw  = (tid & 3) * 4;      // word offset 0,4,8,12
    const int brow = tid >> 1;           // 0..255
    const int bkw  = (tid & 1) * 8;

    const float* Ag0 = U + (size_t)(mt0 + arow) * CC + akw * 2;
    const unsigned* Bg0 = g_Fh2 + ((size_t)(b * OUTC + brow) << 7) + bkw;

    float4 fa[2];
    uint4 fb[2];
    fa[0] = *(const float4*)Ag0;
    fa[1] = *(const float4*)(Ag0 + 4);
    fb[0] = *(const uint4*)Bg0;
    fb[1] = *(const uint4*)(Bg0 + 4);

    for (int c = 0; c < 8; c++) {
        const int buf = c & 1;
        unsigned* As2 = Abuf[buf];
        unsigned* Bs2 = Bbuf[buf];
        uint4 aw;
        aw.x = packh2(fa[0].x, fa[0].y); aw.y = packh2(fa[0].z, fa[0].w);
        aw.z = packh2(fa[1].x, fa[1].y); aw.w = packh2(fa[1].z, fa[1].w);
        *(uint4*)&As2[arow * 20 + akw]     = aw;
        *(uint4*)&Bs2[brow * 20 + bkw]     = fb[0];
        *(uint4*)&Bs2[brow * 20 + bkw + 4] = fb[1];
        __syncthreads();

        if (c < 7) {
            const float* Ag = Ag0 + (c + 1) * 32;
            fa[0] = *(const float4*)Ag;
            fa[1] = *(const float4*)(Ag + 4);
            const unsigned* Bg = Bg0 + (c + 1) * 16;
            fb[0] = *(const uint4*)Bg;
            fb[1] = *(const uint4*)(Bg + 4);
        }

        #pragma unroll
        for (int ks = 0; ks < 2; ks++) {
            const int kb = ks * 8;
            unsigned a0[2], a1[2], a2[2], a3[2];
            #pragma unroll
            for (int mi = 0; mi < 2; mi++) {
                const int mr = warp_m * 32 + mi * 16;
                a0[mi] = As2[(mr + gr) * 20 + kb + tc];
                a1[mi] = As2[(mr + gr + 8) * 20 + kb + tc];
                a2[mi] = As2[(mr + gr) * 20 + kb + tc + 4];
                a3[mi] = As2[(mr + gr + 8) * 20 + kb + tc + 4];
            }
            #pragma unroll
            for (int ni = 0; ni < 8; ni++) {
                const int nb = warp_n * 64 + ni * 8;
                unsigned b0 = Bs2[(nb + gr) * 20 + kb + tc];
                unsigned b1 = Bs2[(nb + gr) * 20 + kb + tc + 4];
                #pragma unroll
                for (int mi = 0; mi < 2; mi++)
                    MMA16(acc[mi][ni], a0[mi], a1[mi], a2[mi], a3[mi], b0, b1);
            }
        }
    }

    #pragma unroll
    for (int mi = 0; mi < 2; mi++) {
        const int orow = mt0 + warp_m * 32 + mi * 16 + gr;
        #pragma unroll
        for (int ni = 0; ni < 8; ni++) {
            const int col = warp_n * 64 + ni * 8 + tc * 2;
            const float2 bb = *(const float2*)(bo + col);
            float2 o0v, o1v;
            o0v.x = acc[mi][ni][0] + bb.x;
            o0v.y = acc[mi][ni][1] + bb.y;
            o1v.x = acc[mi][ni][2] + bb.x;
            o1v.y = acc[mi][ni][3] + bb.y;
            *(float2*)(out + (size_t)orow * OUTC + col) = o0v;
            *(float2*)(out + (size_t)(orow + 8) * OUTC + col) = o1v;
        }
    }
}

// ---------------------------------------------------------------------------
extern "C" void kernel_launch(void* const* d_in, const int* in_sizes, int n_in,
                              void* d_out, int out_size) {
    const float* u  = (const float*)d_in[0];
    // d_in[1] = pos_src -- unused by the reference computation
    const float* Wq = (const float*)d_in[2];
    const float* Wk = (const float*)d_in[3];
    const float* Wv = (const float*)d_in[4];
    const float* Wo = (const float*)d_in[5];
    const float* bo = (const float*)d_in[6];
    float* out = (float*)d_out;

    static int smem_set = 0;
    if (!smem_set) {
        cudaFuncSetAttribute(k4_mma, cudaFuncAttributeMaxDynamicSharedMemorySize, K4_SMEM);
        smem_set = 1;
    }

    k_g  <<<dim3(3, NCH, BB), 256>>>(u);
    kA   <<<dim3(CC, BB), 256>>>();
    kB1  <<<dim3(BB * HH, 2, 4), 256>>>(Wk, Wv);
    kB2T <<<dim3(4, BB * HH), 256>>>(Wv, Wq);
    k3c_F<<<dim3(4, 4, BB), 256>>>(Wo);
    k4_mma<<<512, 512, K4_SMEM>>>(u, bo, out);
}